// round 6
// baseline (speedup 1.0000x reference)
#include <cuda_runtime.h>

// Shapes fixed by dataset: pred/target (8, 3, 1024, 1024) float32
#define HH 1024
#define WW 1024
#define PLANE (HH * WW)          // 2^20
#define NPIX (8 * PLANE)         // 8 * 2^20
#define NQ (NPIX / 4)            // float4 granules
#define NT 256
#define NB_LOSS 2048
#define VSTRIPS (HH / 8)         // 128 strips of 8 rows

// Scratch: __device__ globals (allocation-free rule)
__device__ float g_buf0[NPIX];   // edge_soft
__device__ float g_buf1[NPIX];   // dilated (11x11 max of edge_soft)
__device__ float g_buf2[NPIX];   // crevice mask (pre post-dilation)
__device__ float g_part[NB_LOSS * 3];

__device__ __forceinline__ int clampi(int v, int lo, int hi) {
    return max(lo, min(v, hi));
}
__device__ __forceinline__ float4 f4max(float4 a, float4 b) {
    return make_float4(fmaxf(a.x, b.x), fmaxf(a.y, b.y),
                       fmaxf(a.z, b.z), fmaxf(a.w, b.w));
}
__device__ __forceinline__ float4 f4min(float4 a, float4 b) {
    return make_float4(fminf(a.x, b.x), fminf(a.y, b.y),
                       fminf(a.z, b.z), fminf(a.w, b.w));
}

// ========== K1: Sobel edge_soft (zero-padded conv) -> g_buf0 ================
__global__ void __launch_bounds__(NT) k_edge(const float* __restrict__ t) {
    int i = blockIdx.x * NT + threadIdx.x;
    if (i >= NQ) return;
    int idx = i * 4;
    int b = idx >> 20;
    int y = (idx >> 10) & (HH - 1);
    int x = idx & (WW - 1);
    const float* base = t + (size_t)b * 3 * PLANE + (size_t)y * WW + x;
    bool ym = y > 0, yp = y < HH - 1;
    bool xm = x > 0, xp = (x + 4) < WW;
    float best0 = 0.f, best1 = 0.f, best2 = 0.f, best3 = 0.f;
#pragma unroll
    for (int c = 0; c < 3; c++) {
        const float* pc = base + (size_t)c * PLANE;
        float r[3][6];
        const float* rows[3] = {pc - WW, pc, pc + WW};
        bool oky[3] = {ym, true, yp};
#pragma unroll
        for (int rr = 0; rr < 3; rr++) {
            if (oky[rr]) {
                float4 m = *reinterpret_cast<const float4*>(rows[rr]);
                r[rr][0] = xm ? rows[rr][-1] : 0.f;
                r[rr][1] = m.x; r[rr][2] = m.y; r[rr][3] = m.z; r[rr][4] = m.w;
                r[rr][5] = xp ? rows[rr][4] : 0.f;
            } else {
#pragma unroll
                for (int k = 0; k < 6; k++) r[rr][k] = 0.f;
            }
        }
        float bj[4];
#pragma unroll
        for (int j = 0; j < 4; j++) {
            float gx = (r[0][j + 2] - r[0][j]) + 2.f * (r[1][j + 2] - r[1][j]) +
                       (r[2][j + 2] - r[2][j]);
            float gy = (r[2][j] + 2.f * r[2][j + 1] + r[2][j + 2]) -
                       (r[0][j] + 2.f * r[0][j + 1] + r[0][j + 2]);
            bj[j] = fabsf(gx) + fabsf(gy);
        }
        best0 = fmaxf(best0, bj[0]); best1 = fmaxf(best1, bj[1]);
        best2 = fmaxf(best2, bj[2]); best3 = fmaxf(best3, bj[3]);
    }
    float4 e;
    e.x = fminf(best0 * 2.f, 1.f);   // clip(edge/0.5, 0, 1), edge >= 0
    e.y = fminf(best1 * 2.f, 1.f);
    e.z = fminf(best2 * 2.f, 1.f);
    e.w = fminf(best3 * 2.f, 1.f);
    *reinterpret_cast<float4*>(g_buf0 + idx) = e;
}

// ===== Fused direction-pair strip kernels ===================================
// Block = one 8-row strip of one batch image, full width. For each of 18
// clamped input rows: stage the raw row in a border-replicated padded smem
// buffer (double-buffered, one barrier per row), apply the 11-wide horizontal
// max/min into a register window r[k], then produce 8 output rows via a
// sliding vertical 11-max/min.
// Padded smem: index p <-> logical p-8; pads replicate logical 0 / WW-1,
// which equals clamped-window semantics for max and min.

template <bool MAXOP>
__device__ __forceinline__ float4 hwin11(const float* __restrict__ srow, int x) {
    float v[20];
#pragma unroll
    for (int t4 = 0; t4 < 5; t4++) {
        float4 q = *reinterpret_cast<const float4*>(srow + x + t4 * 4);
        v[t4 * 4 + 0] = q.x; v[t4 * 4 + 1] = q.y;
        v[t4 * 4 + 2] = q.z; v[t4 * 4 + 3] = q.w;
    }
    // v[t] = logical x-8+t. Output j window: v[j+3 .. j+13]. Common: v[6..13].
    float c = v[6];
#pragma unroll
    for (int k = 7; k <= 13; k++) c = MAXOP ? fmaxf(c, v[k]) : fminf(c, v[k]);
    float4 o;
    if (MAXOP) {
        o.x = fmaxf(c, fmaxf(v[3], fmaxf(v[4], v[5])));
        o.y = fmaxf(c, fmaxf(v[4], fmaxf(v[5], v[14])));
        o.z = fmaxf(c, fmaxf(v[5], fmaxf(v[14], v[15])));
        o.w = fmaxf(c, fmaxf(v[14], fmaxf(v[15], v[16])));
    } else {
        o.x = fminf(c, fminf(v[3], fminf(v[4], v[5])));
        o.y = fminf(c, fminf(v[4], fminf(v[5], v[14])));
        o.z = fminf(c, fminf(v[5], fminf(v[14], v[15])));
        o.w = fminf(c, fminf(v[14], fminf(v[15], v[16])));
    }
    return o;
}

// Stage one clamped input row into padded smem buffer (no barrier inside).
__device__ __forceinline__ void stage_row(const float* __restrict__ img,
                                          int yy, int x, float* __restrict__ srow) {
    float4 q = *reinterpret_cast<const float4*>(img + yy * WW + x);
    *reinterpret_cast<float4*>(srow + 8 + x) = q;
    if (threadIdx.x == 0) {
#pragma unroll
        for (int p = 0; p < 8; p++) srow[p] = q.x;
    }
    if (threadIdx.x == NT - 1) {
#pragma unroll
        for (int p = 0; p < 8; p++) srow[WW + 8 + p] = q.w;
    }
}

// K2: h-dilate + v-max (g_buf0 -> g_buf1)
__global__ void __launch_bounds__(NT) k_hdil_vmax() {
    __shared__ float srow[2][WW + 16];
    int blk = blockIdx.x;                  // 0..1023
    int ys = blk & (VSTRIPS - 1);
    int b = blk >> 7;
    int y0 = ys * 8;
    int x = threadIdx.x * 4;
    const float* in = g_buf0 + b * PLANE;
    float* out = g_buf1 + b * PLANE;
    float4 r[18];
#pragma unroll
    for (int k = 0; k < 18; k++) {
        int yy = clampi(y0 - 5 + k, 0, HH - 1);
        stage_row(in, yy, x, srow[k & 1]);
        __syncthreads();
        r[k] = hwin11<true>(srow[k & 1], x);
    }
#pragma unroll
    for (int j = 0; j < 8; j++) {
        float4 m = r[j];
#pragma unroll
        for (int k = 1; k <= 10; k++) m = f4max(m, r[j + k]);
        *reinterpret_cast<float4*>(out + (y0 + j) * WW + x) = m;
    }
}

// K3: h-min + v-min + mask = relu(closed - edge_soft)  (g_buf1 -> g_buf2)
__global__ void __launch_bounds__(NT) k_hmin_vmin_mask() {
    __shared__ float srow[2][WW + 16];
    int blk = blockIdx.x;
    int ys = blk & (VSTRIPS - 1);
    int b = blk >> 7;
    int y0 = ys * 8;
    int x = threadIdx.x * 4;
    const float* in = g_buf1 + b * PLANE;
    const float* ed = g_buf0 + b * PLANE;
    float* out = g_buf2 + b * PLANE;
    float4 r[18];
#pragma unroll
    for (int k = 0; k < 18; k++) {
        int yy = clampi(y0 - 5 + k, 0, HH - 1);
        stage_row(in, yy, x, srow[k & 1]);
        __syncthreads();
        r[k] = hwin11<false>(srow[k & 1], x);
    }
#pragma unroll
    for (int j = 0; j < 8; j++) {
        float4 m = r[j];
#pragma unroll
        for (int k = 1; k <= 10; k++) m = f4min(m, r[j + k]);
        float4 e = *reinterpret_cast<const float4*>(ed + (y0 + j) * WW + x);
        m.x = fmaxf(m.x - e.x, 0.f); m.y = fmaxf(m.y - e.y, 0.f);
        m.z = fmaxf(m.z - e.z, 0.f); m.w = fmaxf(m.w - e.w, 0.f);
        *reinterpret_cast<float4*>(out + (y0 + j) * WW + x) = m;
    }
}

// ---------------- OKLab a,b (L channel is dead code) -------------------------
__device__ __forceinline__ float s2l(float x) {
    x = __saturatef(x);
    return (x <= 0.04045f) ? x * (1.0f / 12.92f)
                           : powf((x + 0.055f) * (1.0f / 1.055f), 2.4f);
}
__device__ __forceinline__ void oklab_ab(float r, float g, float b,
                                         float* oa, float* ob) {
    r = s2l(r); g = s2l(g); b = s2l(b);
    float l = 0.4122214708f * r + 0.5363325363f * g + 0.0514459929f * b;
    float m = 0.2119034982f * r + 0.6806995451f * g + 0.1073969566f * b;
    float s = 0.0883024619f * r + 0.2817188376f * g + 0.6299787005f * b;
    l = cbrtf(fmaxf(l, 1e-10f));
    m = cbrtf(fmaxf(m, 1e-10f));
    s = cbrtf(fmaxf(s, 1e-10f));
    *oa = 1.9779984951f * l - 2.428592205f * m + 0.4505937099f * s;
    *ob = 0.0259040371f * l + 0.7827717662f * m - 0.808675766f * s;
}

// ========== K4: 5x5 post-dilation (separable, 4x4 tile/thread) + loss =======
// Task = one 4-row x 4-col tile. Load 8 clamped mask rows once (3 float4
// each), horizontal 5-max per row -> hrow[8], vertical 5-max -> 4 output
// rows. Mask traffic: 6 float4/quad (was 15).
__global__ void __launch_bounds__(NT) k_loss(const float* __restrict__ pred,
                                             const float* __restrict__ target) {
    int t = blockIdx.x * NT + threadIdx.x;   // 524288 tasks, exact grid
    int xq = t & 255;
    int y4 = (t >> 8) & 255;
    int b = t >> 16;
    int x = xq * 4;
    int y0 = y4 * 4;
    const float* mp = g_buf2 + b * PLANE;

    float4 hrow[8];
    if (x >= 4 && x + 7 < WW) {
        // interior fast path: aligned A|B|C float4 per row, +-2 window
#pragma unroll
        for (int k = 0; k < 8; k++) {
            int ry = clampi(y0 - 2 + k, 0, HH - 1);
            const float* rp = mp + ry * WW + x;
            float4 A = *reinterpret_cast<const float4*>(rp - 4);
            float4 B = *reinterpret_cast<const float4*>(rp);
            float4 C = *reinterpret_cast<const float4*>(rp + 4);
            float bxy = fmaxf(B.x, B.y), bzw = fmaxf(B.z, B.w);
            float4 h;
            h.x = fmaxf(fmaxf(A.z, A.w), fmaxf(bxy, B.z));
            h.y = fmaxf(A.w, fmaxf(bxy, bzw));
            h.z = fmaxf(fmaxf(bxy, bzw), C.x);
            h.w = fmaxf(fmaxf(B.y, B.z), fmaxf(B.w, fmaxf(C.x, C.y)));
            hrow[k] = h;
        }
    } else {
        // border quads: scalar clamped +-2 window per row
#pragma unroll
        for (int k = 0; k < 8; k++) {
            int ry = clampi(y0 - 2 + k, 0, HH - 1);
            const float* rp = mp + ry * WW;
            float hh[4];
#pragma unroll
            for (int j = 0; j < 4; j++) {
                float m = 0.f;                  // mask >= 0, init 0 safe
#pragma unroll
                for (int dx = -2; dx <= 2; dx++)
                    m = fmaxf(m, rp[clampi(x + j + dx, 0, WW - 1)]);
                hh[j] = m;
            }
            hrow[k] = make_float4(hh[0], hh[1], hh[2], hh[3]);
        }
    }

    float sm = 0.f, sc = 0.f, sh = 0.f;
#pragma unroll
    for (int jr = 0; jr < 4; jr++) {
        float4 m4 = hrow[jr];
#pragma unroll
        for (int k = 1; k < 5; k++) m4 = f4max(m4, hrow[jr + k]);
        float mm[4] = {m4.x, m4.y, m4.z, m4.w};
        size_t off = (size_t)b * 3 * PLANE + (size_t)(y0 + jr) * WW + x;
#pragma unroll
        for (int j = 0; j < 4; j++) {
            float m = mm[j];
            if (m > 0.f) {
                sm += m;
                float pa, pb, ta, tb;
                oklab_ab(pred[off + j], pred[off + j + PLANE],
                         pred[off + j + 2 * PLANE], &pa, &pb);
                oklab_ab(target[off + j], target[off + j + PLANE],
                         target[off + j + 2 * PLANE], &ta, &tb);
                float Cp = sqrtf(pa * pa + pb * pb + 1e-12f);
                float Cg = sqrtf(ta * ta + tb * tb + 1e-12f);
                sc += fabsf(Cp - Cg) * m;
                float cosd = (pa * ta + pb * tb) / (Cp * Cg + 1e-12f);
                cosd = fminf(fmaxf(cosd, -1.f), 1.f);
                sh += fmaxf(Cg, 0.01f) * (1.f - cosd) * m;
            }
        }
    }

    __shared__ float sdat[3][NT];
    sdat[0][threadIdx.x] = sm;
    sdat[1][threadIdx.x] = sc;
    sdat[2][threadIdx.x] = sh;
    __syncthreads();
    for (int st = NT / 2; st > 0; st >>= 1) {
        if (threadIdx.x < st) {
            sdat[0][threadIdx.x] += sdat[0][threadIdx.x + st];
            sdat[1][threadIdx.x] += sdat[1][threadIdx.x + st];
            sdat[2][threadIdx.x] += sdat[2][threadIdx.x + st];
        }
        __syncthreads();
    }
    if (threadIdx.x == 0) {
        g_part[blockIdx.x * 3 + 0] = sdat[0][0];
        g_part[blockIdx.x * 3 + 1] = sdat[1][0];
        g_part[blockIdx.x * 3 + 2] = sdat[2][0];
    }
}

// ========== K5: deterministic fp64 finalize =================================
__global__ void __launch_bounds__(NT) k_final(float* __restrict__ out) {
    __shared__ double sd[3][NT];
    double s0 = 0.0, s1 = 0.0, s2 = 0.0;
    for (int i = threadIdx.x; i < NB_LOSS; i += NT) {
        s0 += (double)g_part[3 * i + 0];
        s1 += (double)g_part[3 * i + 1];
        s2 += (double)g_part[3 * i + 2];
    }
    sd[0][threadIdx.x] = s0;
    sd[1][threadIdx.x] = s1;
    sd[2][threadIdx.x] = s2;
    __syncthreads();
    for (int st = NT / 2; st > 0; st >>= 1) {
        if (threadIdx.x < st) {
            sd[0][threadIdx.x] += sd[0][threadIdx.x + st];
            sd[1][threadIdx.x] += sd[1][threadIdx.x + st];
            sd[2][threadIdx.x] += sd[2][threadIdx.x + st];
        }
        __syncthreads();
    }
    if (threadIdx.x == 0) {
        double ms = sd[0][0];
        if (ms < 1.0) ms = 1.0;
        out[0] = (float)((sd[1][0] + 2.0 * sd[2][0]) / ms);
    }
}

extern "C" void kernel_launch(void* const* d_in, const int* in_sizes, int n_in,
                              void* d_out, int out_size) {
    const float* pred = (const float*)d_in[0];
    const float* target = (const float*)d_in[1];
    float* out = (float*)d_out;

    int strip_blocks = 8 * VSTRIPS;            // 1024

    k_edge<<<NQ / NT, NT>>>(target);           // target -> buf0 (edge_soft)
    k_hdil_vmax<<<strip_blocks, NT>>>();       // buf0 -> buf1 (11x11 dilate)
    k_hmin_vmin_mask<<<strip_blocks, NT>>>();  // buf1,buf0 -> buf2 (mask)
    k_loss<<<NB_LOSS, NT>>>(pred, target);     // 5x5 dilate + OKLab loss
    k_final<<<1, NT>>>(out);
}

// round 13
// speedup vs baseline: 2.8539x; 2.8539x over previous
#include <cuda_runtime.h>

// Shapes fixed by dataset: pred/target (8, 3, 1024, 1024) float32
#define HH 1024
#define WW 1024
#define PLANE (HH * WW)          // 2^20
#define NPIX (8 * PLANE)         // 8 * 2^20
#define NQ (NPIX / 4)            // float4 granules
#define NT 256
#define NB_LOSS 2048
#define VSTRIPS (HH / 8)         // 128 strips of 8 rows

// Scratch: __device__ globals (allocation-free rule)
__device__ float g_buf0[NPIX];   // edge_soft
__device__ float g_buf1[NPIX];   // dilated (11x11 max of edge_soft)
__device__ float g_buf2[NPIX];   // crevice mask (pre post-dilation)
__device__ float g_part[NB_LOSS * 3];

__device__ __forceinline__ int clampi(int v, int lo, int hi) {
    return max(lo, min(v, hi));
}
__device__ __forceinline__ float4 f4max(float4 a, float4 b) {
    return make_float4(fmaxf(a.x, b.x), fmaxf(a.y, b.y),
                       fmaxf(a.z, b.z), fmaxf(a.w, b.w));
}
__device__ __forceinline__ float4 f4min(float4 a, float4 b) {
    return make_float4(fminf(a.x, b.x), fminf(a.y, b.y),
                       fminf(a.z, b.z), fminf(a.w, b.w));
}

// ========== K1: Sobel edge_soft (zero-padded conv) -> g_buf0 ================
__global__ void __launch_bounds__(NT) k_edge(const float* __restrict__ t) {
    int i = blockIdx.x * NT + threadIdx.x;
    if (i >= NQ) return;
    int idx = i * 4;
    int b = idx >> 20;
    int y = (idx >> 10) & (HH - 1);
    int x = idx & (WW - 1);
    const float* base = t + (size_t)b * 3 * PLANE + (size_t)y * WW + x;
    bool ym = y > 0, yp = y < HH - 1;
    bool xm = x > 0, xp = (x + 4) < WW;
    float best0 = 0.f, best1 = 0.f, best2 = 0.f, best3 = 0.f;
#pragma unroll
    for (int c = 0; c < 3; c++) {
        const float* pc = base + (size_t)c * PLANE;
        float r[3][6];
        const float* rows[3] = {pc - WW, pc, pc + WW};
        bool oky[3] = {ym, true, yp};
#pragma unroll
        for (int rr = 0; rr < 3; rr++) {
            if (oky[rr]) {
                float4 m = *reinterpret_cast<const float4*>(rows[rr]);
                r[rr][0] = xm ? rows[rr][-1] : 0.f;
                r[rr][1] = m.x; r[rr][2] = m.y; r[rr][3] = m.z; r[rr][4] = m.w;
                r[rr][5] = xp ? rows[rr][4] : 0.f;
            } else {
#pragma unroll
                for (int k = 0; k < 6; k++) r[rr][k] = 0.f;
            }
        }
        float bj[4];
#pragma unroll
        for (int j = 0; j < 4; j++) {
            float gx = (r[0][j + 2] - r[0][j]) + 2.f * (r[1][j + 2] - r[1][j]) +
                       (r[2][j + 2] - r[2][j]);
            float gy = (r[2][j] + 2.f * r[2][j + 1] + r[2][j + 2]) -
                       (r[0][j] + 2.f * r[0][j + 1] + r[0][j + 2]);
            bj[j] = fabsf(gx) + fabsf(gy);
        }
        best0 = fmaxf(best0, bj[0]); best1 = fmaxf(best1, bj[1]);
        best2 = fmaxf(best2, bj[2]); best3 = fmaxf(best3, bj[3]);
    }
    float4 e;
    e.x = fminf(best0 * 2.f, 1.f);   // clip(edge/0.5, 0, 1), edge >= 0
    e.y = fminf(best1 * 2.f, 1.f);
    e.z = fminf(best2 * 2.f, 1.f);
    e.w = fminf(best3 * 2.f, 1.f);
    *reinterpret_cast<float4*>(g_buf0 + idx) = e;
}

// ===== Fused direction-pair strip kernels ===================================
template <bool MAXOP>
__device__ __forceinline__ float4 hwin11(const float* __restrict__ srow, int x) {
    float v[20];
#pragma unroll
    for (int t4 = 0; t4 < 5; t4++) {
        float4 q = *reinterpret_cast<const float4*>(srow + x + t4 * 4);
        v[t4 * 4 + 0] = q.x; v[t4 * 4 + 1] = q.y;
        v[t4 * 4 + 2] = q.z; v[t4 * 4 + 3] = q.w;
    }
    // v[t] = logical x-8+t. Output j window: v[j+3 .. j+13]. Common: v[6..13].
    float c = v[6];
#pragma unroll
    for (int k = 7; k <= 13; k++) c = MAXOP ? fmaxf(c, v[k]) : fminf(c, v[k]);
    float4 o;
    if (MAXOP) {
        o.x = fmaxf(c, fmaxf(v[3], fmaxf(v[4], v[5])));
        o.y = fmaxf(c, fmaxf(v[4], fmaxf(v[5], v[14])));
        o.z = fmaxf(c, fmaxf(v[5], fmaxf(v[14], v[15])));
        o.w = fmaxf(c, fmaxf(v[14], fmaxf(v[15], v[16])));
    } else {
        o.x = fminf(c, fminf(v[3], fminf(v[4], v[5])));
        o.y = fminf(c, fminf(v[4], fminf(v[5], v[14])));
        o.z = fminf(c, fminf(v[5], fminf(v[14], v[15])));
        o.w = fminf(c, fminf(v[14], fminf(v[15], v[16])));
    }
    return o;
}

__device__ __forceinline__ void stage_row(const float* __restrict__ img,
                                          int yy, int x, float* __restrict__ srow) {
    float4 q = *reinterpret_cast<const float4*>(img + yy * WW + x);
    *reinterpret_cast<float4*>(srow + 8 + x) = q;
    if (threadIdx.x == 0) {
#pragma unroll
        for (int p = 0; p < 8; p++) srow[p] = q.x;
    }
    if (threadIdx.x == NT - 1) {
#pragma unroll
        for (int p = 0; p < 8; p++) srow[WW + 8 + p] = q.w;
    }
}

// K2: h-dilate + v-max (g_buf0 -> g_buf1)
__global__ void __launch_bounds__(NT) k_hdil_vmax() {
    __shared__ float srow[2][WW + 16];
    int blk = blockIdx.x;                  // 0..1023
    int ys = blk & (VSTRIPS - 1);
    int b = blk >> 7;
    int y0 = ys * 8;
    int x = threadIdx.x * 4;
    const float* in = g_buf0 + b * PLANE;
    float* out = g_buf1 + b * PLANE;
    float4 r[18];
#pragma unroll
    for (int k = 0; k < 18; k++) {
        int yy = clampi(y0 - 5 + k, 0, HH - 1);
        stage_row(in, yy, x, srow[k & 1]);
        __syncthreads();
        r[k] = hwin11<true>(srow[k & 1], x);
    }
#pragma unroll
    for (int j = 0; j < 8; j++) {
        float4 m = r[j];
#pragma unroll
        for (int k = 1; k <= 10; k++) m = f4max(m, r[j + k]);
        *reinterpret_cast<float4*>(out + (y0 + j) * WW + x) = m;
    }
}

// K3: h-min + v-min + mask = relu(closed - edge_soft)  (g_buf1 -> g_buf2)
__global__ void __launch_bounds__(NT) k_hmin_vmin_mask() {
    __shared__ float srow[2][WW + 16];
    int blk = blockIdx.x;
    int ys = blk & (VSTRIPS - 1);
    int b = blk >> 7;
    int y0 = ys * 8;
    int x = threadIdx.x * 4;
    const float* in = g_buf1 + b * PLANE;
    const float* ed = g_buf0 + b * PLANE;
    float* out = g_buf2 + b * PLANE;
    float4 r[18];
#pragma unroll
    for (int k = 0; k < 18; k++) {
        int yy = clampi(y0 - 5 + k, 0, HH - 1);
        stage_row(in, yy, x, srow[k & 1]);
        __syncthreads();
        r[k] = hwin11<false>(srow[k & 1], x);
    }
#pragma unroll
    for (int j = 0; j < 8; j++) {
        float4 m = r[j];
#pragma unroll
        for (int k = 1; k <= 10; k++) m = f4min(m, r[j + k]);
        float4 e = *reinterpret_cast<const float4*>(ed + (y0 + j) * WW + x);
        m.x = fmaxf(m.x - e.x, 0.f); m.y = fmaxf(m.y - e.y, 0.f);
        m.z = fmaxf(m.z - e.z, 0.f); m.w = fmaxf(m.w - e.w, 0.f);
        *reinterpret_cast<float4*>(out + (y0 + j) * WW + x) = m;
    }
}

// ---------------- OKLab a,b — fast MUFU transcendentals ---------------------
__device__ __forceinline__ float fast_cbrt(float x) {   // x >= 1e-10
    return __expf(0.3333333333f * __logf(x));
}
__device__ __forceinline__ float s2l(float x) {
    x = __saturatef(x);
    float y = __expf(2.4f * __logf((x + 0.055f) * (1.0f / 1.055f)));
    return (x <= 0.04045f) ? x * (1.0f / 12.92f) : y;
}
__device__ __forceinline__ void oklab_ab(float r, float g, float b,
                                         float* oa, float* ob) {
    r = s2l(r); g = s2l(g); b = s2l(b);
    float l = 0.4122214708f * r + 0.5363325363f * g + 0.0514459929f * b;
    float m = 0.2119034982f * r + 0.6806995451f * g + 0.1073969566f * b;
    float s = 0.0883024619f * r + 0.2817188376f * g + 0.6299787005f * b;
    l = fast_cbrt(fmaxf(l, 1e-10f));
    m = fast_cbrt(fmaxf(m, 1e-10f));
    s = fast_cbrt(fmaxf(s, 1e-10f));
    *oa = 1.9779984951f * l - 2.428592205f * m + 0.4505937099f * s;
    *ob = 0.0259040371f * l + 0.7827717662f * m - 0.808675766f * s;
}

// ========== K4: 5x5 post-dilation + warp-compacted masked loss ==============
// Phase A: per-thread 4x4 tile mask via separable 5-max; ballot-compact
// active (pixel, mask) pairs into per-warp smem lists (fixed (iter, lane)
// order -> deterministic). Phase B: process lists 32-wide with full lanes.
__global__ void __launch_bounds__(NT) k_loss(const float* __restrict__ pred,
                                             const float* __restrict__ target) {
    __shared__ unsigned short sidx[8][512];
    __shared__ float smv[8][512];
    int t = blockIdx.x * NT + threadIdx.x;   // 524288 tasks, exact grid
    int xq = t & 255;
    int y4 = (t >> 8) & 255;
    int b = t >> 16;
    int x = xq * 4;
    int y0 = y4 * 4;
    int w = threadIdx.x >> 5;
    int lane = threadIdx.x & 31;
    unsigned lmask = (1u << lane) - 1u;
    const float* mp = g_buf2 + b * PLANE;

    float4 hrow[8];
    if (x >= 4 && x + 7 < WW) {
#pragma unroll
        for (int k = 0; k < 8; k++) {
            int ry = clampi(y0 - 2 + k, 0, HH - 1);
            const float* rp = mp + ry * WW + x;
            float4 A = *reinterpret_cast<const float4*>(rp - 4);
            float4 B = *reinterpret_cast<const float4*>(rp);
            float4 C = *reinterpret_cast<const float4*>(rp + 4);
            float bxy = fmaxf(B.x, B.y), bzw = fmaxf(B.z, B.w);
            float4 h;
            h.x = fmaxf(fmaxf(A.z, A.w), fmaxf(bxy, B.z));
            h.y = fmaxf(A.w, fmaxf(bxy, bzw));
            h.z = fmaxf(fmaxf(bxy, bzw), C.x);
            h.w = fmaxf(fmaxf(B.y, B.z), fmaxf(B.w, fmaxf(C.x, C.y)));
            hrow[k] = h;
        }
    } else {
#pragma unroll
        for (int k = 0; k < 8; k++) {
            int ry = clampi(y0 - 2 + k, 0, HH - 1);
            const float* rp = mp + ry * WW;
            float hh[4];
#pragma unroll
            for (int j = 0; j < 4; j++) {
                float m = 0.f;                  // mask >= 0, init 0 safe
#pragma unroll
                for (int dx = -2; dx <= 2; dx++)
                    m = fmaxf(m, rp[clampi(x + j + dx, 0, WW - 1)]);
                hh[j] = m;
            }
            hrow[k] = make_float4(hh[0], hh[1], hh[2], hh[3]);
        }
    }

    // Phase A: mask sum + compaction
    float sm = 0.f;
    int cnt = 0;
#pragma unroll
    for (int jr = 0; jr < 4; jr++) {
        float4 m4 = hrow[jr];
#pragma unroll
        for (int k = 1; k < 5; k++) m4 = f4max(m4, hrow[jr + k]);
        float mm[4] = {m4.x, m4.y, m4.z, m4.w};
#pragma unroll
        for (int j = 0; j < 4; j++) {
            float m = mm[j];
            sm += m;
            bool act = m > 0.f;
            unsigned bal = __ballot_sync(0xffffffffu, act);
            if (act) {
                int pos = cnt + __popc(bal & lmask);
                sidx[w][pos] = (unsigned short)((lane << 4) | (jr << 2) | j);
                smv[w][pos] = m;
            }
            cnt += __popc(bal);
        }
    }
    __syncwarp();

    // Phase B: full-lane color processing of compacted list
    float sc = 0.f, sh = 0.f;
    int wxq0 = xq - lane;                      // warp's first x-quad
    size_t cbase = (size_t)b * 3 * PLANE;
    for (int i0 = 0; i0 < cnt; i0 += 32) {
        int i = i0 + lane;
        if (i < cnt) {
            int e = sidx[w][i];
            float m = smv[w][i];
            int ls = e >> 4, jr = (e >> 2) & 3, j = e & 3;
            size_t off = cbase + (size_t)(y0 + jr) * WW + (wxq0 + ls) * 4 + j;
            float pa, pb, ta, tb;
            oklab_ab(pred[off], pred[off + PLANE], pred[off + 2 * PLANE],
                     &pa, &pb);
            oklab_ab(target[off], target[off + PLANE], target[off + 2 * PLANE],
                     &ta, &tb);
            float Cp = sqrtf(pa * pa + pb * pb + 1e-12f);
            float Cg = sqrtf(ta * ta + tb * tb + 1e-12f);
            sc += fabsf(Cp - Cg) * m;
            float cosd = (pa * ta + pb * tb) / (Cp * Cg + 1e-12f);
            cosd = fminf(fmaxf(cosd, -1.f), 1.f);
            sh += fmaxf(Cg, 0.01f) * (1.f - cosd) * m;
        }
    }

    __shared__ float sdat[3][NT];
    sdat[0][threadIdx.x] = sm;
    sdat[1][threadIdx.x] = sc;
    sdat[2][threadIdx.x] = sh;
    __syncthreads();
    for (int st = NT / 2; st > 0; st >>= 1) {
        if (threadIdx.x < st) {
            sdat[0][threadIdx.x] += sdat[0][threadIdx.x + st];
            sdat[1][threadIdx.x] += sdat[1][threadIdx.x + st];
            sdat[2][threadIdx.x] += sdat[2][threadIdx.x + st];
        }
        __syncthreads();
    }
    if (threadIdx.x == 0) {
        g_part[blockIdx.x * 3 + 0] = sdat[0][0];
        g_part[blockIdx.x * 3 + 1] = sdat[1][0];
        g_part[blockIdx.x * 3 + 2] = sdat[2][0];
    }
}

// ========== K5: deterministic fp64 finalize =================================
__global__ void __launch_bounds__(NT) k_final(float* __restrict__ out) {
    __shared__ double sd[3][NT];
    double s0 = 0.0, s1 = 0.0, s2 = 0.0;
    for (int i = threadIdx.x; i < NB_LOSS; i += NT) {
        s0 += (double)g_part[3 * i + 0];
        s1 += (double)g_part[3 * i + 1];
        s2 += (double)g_part[3 * i + 2];
    }
    sd[0][threadIdx.x] = s0;
    sd[1][threadIdx.x] = s1;
    sd[2][threadIdx.x] = s2;
    __syncthreads();
    for (int st = NT / 2; st > 0; st >>= 1) {
        if (threadIdx.x < st) {
            sd[0][threadIdx.x] += sd[0][threadIdx.x + st];
            sd[1][threadIdx.x] += sd[1][threadIdx.x + st];
            sd[2][threadIdx.x] += sd[2][threadIdx.x + st];
        }
        __syncthreads();
    }
    if (threadIdx.x == 0) {
        double ms = sd[0][0];
        if (ms < 1.0) ms = 1.0;
        out[0] = (float)((sd[1][0] + 2.0 * sd[2][0]) / ms);
    }
}

extern "C" void kernel_launch(void* const* d_in, const int* in_sizes, int n_in,
                              void* d_out, int out_size) {
    const float* pred = (const float*)d_in[0];
    const float* target = (const float*)d_in[1];
    float* out = (float*)d_out;

    int strip_blocks = 8 * VSTRIPS;            // 1024

    k_edge<<<NQ / NT, NT>>>(target);           // target -> buf0 (edge_soft)
    k_hdil_vmax<<<strip_blocks, NT>>>();       // buf0 -> buf1 (11x11 dilate)
    k_hmin_vmin_mask<<<strip_blocks, NT>>>();  // buf1,buf0 -> buf2 (mask)
    k_loss<<<NB_LOSS, NT>>>(pred, target);     // 5x5 dilate + compacted loss
    k_final<<<1, NT>>>(out);
}

// round 15
// speedup vs baseline: 3.4799x; 1.2193x over previous
#include <cuda_runtime.h>

// Shapes fixed by dataset: pred/target (8, 3, 1024, 1024) float32
#define HH 1024
#define WW 1024
#define PLANE (HH * WW)          // 2^20
#define NPIX (8 * PLANE)         // 8 * 2^20
#define NQ (NPIX / 4)            // float4 granules
#define NT 256
#define NB_LOSS 2048
#define VSTRIPS (HH / 8)         // 128 strips of 8 rows

// Scratch: __device__ globals (allocation-free rule)
__device__ float g_buf0[NPIX];   // edge_soft
__device__ float g_buf1[NPIX];   // dilated (11x11 max of edge_soft)
__device__ float g_buf2[NPIX];   // crevice mask (pre post-dilation)
__device__ float g_part[NB_LOSS * 3];

__device__ __forceinline__ int clampi(int v, int lo, int hi) {
    return max(lo, min(v, hi));
}
__device__ __forceinline__ float4 f4max(float4 a, float4 b) {
    return make_float4(fmaxf(a.x, b.x), fmaxf(a.y, b.y),
                       fmaxf(a.z, b.z), fmaxf(a.w, b.w));
}
__device__ __forceinline__ float4 f4min(float4 a, float4 b) {
    return make_float4(fminf(a.x, b.x), fminf(a.y, b.y),
                       fminf(a.z, b.z), fminf(a.w, b.w));
}

// ========== K1: Sobel edge_soft (zero-padded conv) -> g_buf0 ================
__global__ void __launch_bounds__(NT) k_edge(const float* __restrict__ t) {
    int i = blockIdx.x * NT + threadIdx.x;
    if (i >= NQ) return;
    int idx = i * 4;
    int b = idx >> 20;
    int y = (idx >> 10) & (HH - 1);
    int x = idx & (WW - 1);
    const float* base = t + (size_t)b * 3 * PLANE + (size_t)y * WW + x;
    bool ym = y > 0, yp = y < HH - 1;
    bool xm = x > 0, xp = (x + 4) < WW;
    float best0 = 0.f, best1 = 0.f, best2 = 0.f, best3 = 0.f;
#pragma unroll
    for (int c = 0; c < 3; c++) {
        const float* pc = base + (size_t)c * PLANE;
        float r[3][6];
        const float* rows[3] = {pc - WW, pc, pc + WW};
        bool oky[3] = {ym, true, yp};
#pragma unroll
        for (int rr = 0; rr < 3; rr++) {
            if (oky[rr]) {
                float4 m = *reinterpret_cast<const float4*>(rows[rr]);
                r[rr][0] = xm ? rows[rr][-1] : 0.f;
                r[rr][1] = m.x; r[rr][2] = m.y; r[rr][3] = m.z; r[rr][4] = m.w;
                r[rr][5] = xp ? rows[rr][4] : 0.f;
            } else {
#pragma unroll
                for (int k = 0; k < 6; k++) r[rr][k] = 0.f;
            }
        }
        float bj[4];
#pragma unroll
        for (int j = 0; j < 4; j++) {
            float gx = (r[0][j + 2] - r[0][j]) + 2.f * (r[1][j + 2] - r[1][j]) +
                       (r[2][j + 2] - r[2][j]);
            float gy = (r[2][j] + 2.f * r[2][j + 1] + r[2][j + 2]) -
                       (r[0][j] + 2.f * r[0][j + 1] + r[0][j + 2]);
            bj[j] = fabsf(gx) + fabsf(gy);
        }
        best0 = fmaxf(best0, bj[0]); best1 = fmaxf(best1, bj[1]);
        best2 = fmaxf(best2, bj[2]); best3 = fmaxf(best3, bj[3]);
    }
    float4 e;
    e.x = fminf(best0 * 2.f, 1.f);   // clip(edge/0.5, 0, 1), edge >= 0
    e.y = fminf(best1 * 2.f, 1.f);
    e.z = fminf(best2 * 2.f, 1.f);
    e.w = fminf(best3 * 2.f, 1.f);
    *reinterpret_cast<float4*>(g_buf0 + idx) = e;
}

// ===== Fused direction-pair strip kernels (pipelined, paired barriers) ======
template <bool MAXOP>
__device__ __forceinline__ float4 hwin11(const float* __restrict__ srow, int x) {
    float v[20];
#pragma unroll
    for (int t4 = 0; t4 < 5; t4++) {
        float4 q = *reinterpret_cast<const float4*>(srow + x + t4 * 4);
        v[t4 * 4 + 0] = q.x; v[t4 * 4 + 1] = q.y;
        v[t4 * 4 + 2] = q.z; v[t4 * 4 + 3] = q.w;
    }
    // v[t] = logical x-8+t. Output j window: v[j+3 .. j+13]. Common: v[6..13].
    float c = v[6];
#pragma unroll
    for (int k = 7; k <= 13; k++) c = MAXOP ? fmaxf(c, v[k]) : fminf(c, v[k]);
    float4 o;
    if (MAXOP) {
        o.x = fmaxf(c, fmaxf(v[3], fmaxf(v[4], v[5])));
        o.y = fmaxf(c, fmaxf(v[4], fmaxf(v[5], v[14])));
        o.z = fmaxf(c, fmaxf(v[5], fmaxf(v[14], v[15])));
        o.w = fmaxf(c, fmaxf(v[14], fmaxf(v[15], v[16])));
    } else {
        o.x = fminf(c, fminf(v[3], fminf(v[4], v[5])));
        o.y = fminf(c, fminf(v[4], fminf(v[5], v[14])));
        o.z = fminf(c, fminf(v[5], fminf(v[14], v[15])));
        o.w = fminf(c, fminf(v[14], fminf(v[15], v[16])));
    }
    return o;
}

// Stage a prefetched row value into a padded smem buffer (no loads inside).
__device__ __forceinline__ void stage_q(float4 q, int x, float* __restrict__ srow) {
    *reinterpret_cast<float4*>(srow + 8 + x) = q;
    if (threadIdx.x == 0) {
#pragma unroll
        for (int p = 0; p < 8; p++) srow[p] = q.x;
    }
    if (threadIdx.x == NT - 1) {
#pragma unroll
        for (int p = 0; p < 8; p++) srow[WW + 8 + p] = q.w;
    }
}

// Streaming vertical accumulator update: output j covers h-rows k in [j, j+10].
// k is compile-time after full unroll, so the guards fold away.
template <bool MAXOP>
__device__ __forceinline__ void vupd(float4* acc, int k, float4 h) {
#pragma unroll
    for (int j = 0; j < 8; j++) {
        if (j <= k && k <= j + 10) {
            if (j == k) acc[j] = h;
            else acc[j] = MAXOP ? f4max(acc[j], h) : f4min(acc[j], h);
        }
    }
}

// K2: h-dilate + v-max (g_buf0 -> g_buf1)
__global__ void __launch_bounds__(NT) k_hdil_vmax() {
    __shared__ float srow[4][WW + 16];
    int blk = blockIdx.x;                  // 0..1023
    int ys = blk & (VSTRIPS - 1);
    int b = blk >> 7;
    int y0 = ys * 8;
    int x = threadIdx.x * 4;
    const float* in = g_buf0 + b * PLANE;
    float* out = g_buf1 + b * PLANE;
    float4 acc[8];
    float4 q0 = *reinterpret_cast<const float4*>(
        in + clampi(y0 - 5, 0, HH - 1) * WW + x);
    float4 q1 = *reinterpret_cast<const float4*>(
        in + clampi(y0 - 4, 0, HH - 1) * WW + x);
#pragma unroll
    for (int p = 0; p < 9; p++) {          // pairs cover rows k = 2p, 2p+1
        float4 n0, n1;
        if (p < 8) {                        // prefetch next pair (overlaps bar+compute)
            n0 = *reinterpret_cast<const float4*>(
                in + clampi(y0 - 5 + 2 * p + 2, 0, HH - 1) * WW + x);
            n1 = *reinterpret_cast<const float4*>(
                in + clampi(y0 - 5 + 2 * p + 3, 0, HH - 1) * WW + x);
        }
        float* s0 = srow[(p & 1) * 2];
        float* s1 = srow[(p & 1) * 2 + 1];
        stage_q(q0, x, s0);
        stage_q(q1, x, s1);
        __syncthreads();
        vupd<true>(acc, 2 * p, hwin11<true>(s0, x));
        vupd<true>(acc, 2 * p + 1, hwin11<true>(s1, x));
        if (p < 8) { q0 = n0; q1 = n1; }
    }
#pragma unroll
    for (int j = 0; j < 8; j++)
        *reinterpret_cast<float4*>(out + (y0 + j) * WW + x) = acc[j];
}

// K3: h-min + v-min + mask = relu(closed - edge_soft)  (g_buf1 -> g_buf2)
__global__ void __launch_bounds__(NT) k_hmin_vmin_mask() {
    __shared__ float srow[4][WW + 16];
    int blk = blockIdx.x;
    int ys = blk & (VSTRIPS - 1);
    int b = blk >> 7;
    int y0 = ys * 8;
    int x = threadIdx.x * 4;
    const float* in = g_buf1 + b * PLANE;
    const float* ed = g_buf0 + b * PLANE;
    float* out = g_buf2 + b * PLANE;
    float4 acc[8];
    float4 q0 = *reinterpret_cast<const float4*>(
        in + clampi(y0 - 5, 0, HH - 1) * WW + x);
    float4 q1 = *reinterpret_cast<const float4*>(
        in + clampi(y0 - 4, 0, HH - 1) * WW + x);
#pragma unroll
    for (int p = 0; p < 9; p++) {
        float4 n0, n1;
        if (p < 8) {
            n0 = *reinterpret_cast<const float4*>(
                in + clampi(y0 - 5 + 2 * p + 2, 0, HH - 1) * WW + x);
            n1 = *reinterpret_cast<const float4*>(
                in + clampi(y0 - 5 + 2 * p + 3, 0, HH - 1) * WW + x);
        }
        float* s0 = srow[(p & 1) * 2];
        float* s1 = srow[(p & 1) * 2 + 1];
        stage_q(q0, x, s0);
        stage_q(q1, x, s1);
        __syncthreads();
        vupd<false>(acc, 2 * p, hwin11<false>(s0, x));
        vupd<false>(acc, 2 * p + 1, hwin11<false>(s1, x));
        if (p < 8) { q0 = n0; q1 = n1; }
    }
#pragma unroll
    for (int j = 0; j < 8; j++) {
        float4 e = *reinterpret_cast<const float4*>(ed + (y0 + j) * WW + x);
        float4 m = acc[j];
        m.x = fmaxf(m.x - e.x, 0.f); m.y = fmaxf(m.y - e.y, 0.f);
        m.z = fmaxf(m.z - e.z, 0.f); m.w = fmaxf(m.w - e.w, 0.f);
        *reinterpret_cast<float4*>(out + (y0 + j) * WW + x) = m;
    }
}

// ---------------- OKLab a,b — fast MUFU transcendentals ---------------------
__device__ __forceinline__ float fast_cbrt(float x) {   // x >= 1e-10
    return __expf(0.3333333333f * __logf(x));
}
__device__ __forceinline__ float s2l(float x) {
    x = __saturatef(x);
    float y = __expf(2.4f * __logf((x + 0.055f) * (1.0f / 1.055f)));
    return (x <= 0.04045f) ? x * (1.0f / 12.92f) : y;
}
__device__ __forceinline__ void oklab_ab(float r, float g, float b,
                                         float* oa, float* ob) {
    r = s2l(r); g = s2l(g); b = s2l(b);
    float l = 0.4122214708f * r + 0.5363325363f * g + 0.0514459929f * b;
    float m = 0.2119034982f * r + 0.6806995451f * g + 0.1073969566f * b;
    float s = 0.0883024619f * r + 0.2817188376f * g + 0.6299787005f * b;
    l = fast_cbrt(fmaxf(l, 1e-10f));
    m = fast_cbrt(fmaxf(m, 1e-10f));
    s = fast_cbrt(fmaxf(s, 1e-10f));
    *oa = 1.9779984951f * l - 2.428592205f * m + 0.4505937099f * s;
    *ob = 0.0259040371f * l + 0.7827717662f * m - 0.808675766f * s;
}

// ========== K4: 5x5 post-dilation + warp-compacted masked loss ==============
__global__ void __launch_bounds__(NT) k_loss(const float* __restrict__ pred,
                                             const float* __restrict__ target) {
    __shared__ unsigned short sidx[8][512];
    __shared__ float smv[8][512];
    int t = blockIdx.x * NT + threadIdx.x;   // 524288 tasks, exact grid
    int xq = t & 255;
    int y4 = (t >> 8) & 255;
    int b = t >> 16;
    int x = xq * 4;
    int y0 = y4 * 4;
    int w = threadIdx.x >> 5;
    int lane = threadIdx.x & 31;
    unsigned lmask = (1u << lane) - 1u;
    const float* mp = g_buf2 + b * PLANE;

    float4 hrow[8];
    if (x >= 4 && x + 7 < WW) {
#pragma unroll
        for (int k = 0; k < 8; k++) {
            int ry = clampi(y0 - 2 + k, 0, HH - 1);
            const float* rp = mp + ry * WW + x;
            float4 A = *reinterpret_cast<const float4*>(rp - 4);
            float4 B = *reinterpret_cast<const float4*>(rp);
            float4 C = *reinterpret_cast<const float4*>(rp + 4);
            float bxy = fmaxf(B.x, B.y), bzw = fmaxf(B.z, B.w);
            float4 h;
            h.x = fmaxf(fmaxf(A.z, A.w), fmaxf(bxy, B.z));
            h.y = fmaxf(A.w, fmaxf(bxy, bzw));
            h.z = fmaxf(fmaxf(bxy, bzw), C.x);
            h.w = fmaxf(fmaxf(B.y, B.z), fmaxf(B.w, fmaxf(C.x, C.y)));
            hrow[k] = h;
        }
    } else {
#pragma unroll
        for (int k = 0; k < 8; k++) {
            int ry = clampi(y0 - 2 + k, 0, HH - 1);
            const float* rp = mp + ry * WW;
            float hh[4];
#pragma unroll
            for (int j = 0; j < 4; j++) {
                float m = 0.f;                  // mask >= 0, init 0 safe
#pragma unroll
                for (int dx = -2; dx <= 2; dx++)
                    m = fmaxf(m, rp[clampi(x + j + dx, 0, WW - 1)]);
                hh[j] = m;
            }
            hrow[k] = make_float4(hh[0], hh[1], hh[2], hh[3]);
        }
    }

    // Phase A: mask sum + compaction
    float sm = 0.f;
    int cnt = 0;
#pragma unroll
    for (int jr = 0; jr < 4; jr++) {
        float4 m4 = hrow[jr];
#pragma unroll
        for (int k = 1; k < 5; k++) m4 = f4max(m4, hrow[jr + k]);
        float mm[4] = {m4.x, m4.y, m4.z, m4.w};
#pragma unroll
        for (int j = 0; j < 4; j++) {
            float m = mm[j];
            sm += m;
            bool act = m > 0.f;
            unsigned bal = __ballot_sync(0xffffffffu, act);
            if (act) {
                int pos = cnt + __popc(bal & lmask);
                sidx[w][pos] = (unsigned short)((lane << 4) | (jr << 2) | j);
                smv[w][pos] = m;
            }
            cnt += __popc(bal);
        }
    }
    __syncwarp();

    // Phase B: full-lane color processing of compacted list
    float sc = 0.f, sh = 0.f;
    int wxq0 = xq - lane;                      // warp's first x-quad
    size_t cbase = (size_t)b * 3 * PLANE;
    for (int i0 = 0; i0 < cnt; i0 += 32) {
        int i = i0 + lane;
        if (i < cnt) {
            int e = sidx[w][i];
            float m = smv[w][i];
            int ls = e >> 4, jr = (e >> 2) & 3, j = e & 3;
            size_t off = cbase + (size_t)(y0 + jr) * WW + (wxq0 + ls) * 4 + j;
            float pa, pb, ta, tb;
            oklab_ab(pred[off], pred[off + PLANE], pred[off + 2 * PLANE],
                     &pa, &pb);
            oklab_ab(target[off], target[off + PLANE], target[off + 2 * PLANE],
                     &ta, &tb);
            float Cp = sqrtf(pa * pa + pb * pb + 1e-12f);
            float Cg = sqrtf(ta * ta + tb * tb + 1e-12f);
            sc += fabsf(Cp - Cg) * m;
            float cosd = (pa * ta + pb * tb) / (Cp * Cg + 1e-12f);
            cosd = fminf(fmaxf(cosd, -1.f), 1.f);
            sh += fmaxf(Cg, 0.01f) * (1.f - cosd) * m;
        }
    }

    __shared__ float sdat[3][NT];
    sdat[0][threadIdx.x] = sm;
    sdat[1][threadIdx.x] = sc;
    sdat[2][threadIdx.x] = sh;
    __syncthreads();
    for (int st = NT / 2; st > 0; st >>= 1) {
        if (threadIdx.x < st) {
            sdat[0][threadIdx.x] += sdat[0][threadIdx.x + st];
            sdat[1][threadIdx.x] += sdat[1][threadIdx.x + st];
            sdat[2][threadIdx.x] += sdat[2][threadIdx.x + st];
        }
        __syncthreads();
    }
    if (threadIdx.x == 0) {
        g_part[blockIdx.x * 3 + 0] = sdat[0][0];
        g_part[blockIdx.x * 3 + 1] = sdat[1][0];
        g_part[blockIdx.x * 3 + 2] = sdat[2][0];
    }
}

// ========== K5: deterministic fp64 finalize =================================
__global__ void __launch_bounds__(NT) k_final(float* __restrict__ out) {
    __shared__ double sd[3][NT];
    double s0 = 0.0, s1 = 0.0, s2 = 0.0;
    for (int i = threadIdx.x; i < NB_LOSS; i += NT) {
        s0 += (double)g_part[3 * i + 0];
        s1 += (double)g_part[3 * i + 1];
        s2 += (double)g_part[3 * i + 2];
    }
    sd[0][threadIdx.x] = s0;
    sd[1][threadIdx.x] = s1;
    sd[2][threadIdx.x] = s2;
    __syncthreads();
    for (int st = NT / 2; st > 0; st >>= 1) {
        if (threadIdx.x < st) {
            sd[0][threadIdx.x] += sd[0][threadIdx.x + st];
            sd[1][threadIdx.x] += sd[1][threadIdx.x + st];
            sd[2][threadIdx.x] += sd[2][threadIdx.x + st];
        }
        __syncthreads();
    }
    if (threadIdx.x == 0) {
        double ms = sd[0][0];
        if (ms < 1.0) ms = 1.0;
        out[0] = (float)((sd[1][0] + 2.0 * sd[2][0]) / ms);
    }
}

extern "C" void kernel_launch(void* const* d_in, const int* in_sizes, int n_in,
                              void* d_out, int out_size) {
    const float* pred = (const float*)d_in[0];
    const float* target = (const float*)d_in[1];
    float* out = (float*)d_out;

    int strip_blocks = 8 * VSTRIPS;            // 1024

    k_edge<<<NQ / NT, NT>>>(target);           // target -> buf0 (edge_soft)
    k_hdil_vmax<<<strip_blocks, NT>>>();       // buf0 -> buf1 (11x11 dilate)
    k_hmin_vmin_mask<<<strip_blocks, NT>>>();  // buf1,buf0 -> buf2 (mask)
    k_loss<<<NB_LOSS, NT>>>(pred, target);     // 5x5 dilate + compacted loss
    k_final<<<1, NT>>>(out);
}